// round 2
// baseline (speedup 1.0000x reference)
#include <cuda_runtime.h>

// Problem constants
#define T_STEPS  128
#define IN_SZ    32
#define HID      64
#define GATES    256     // 4*HID
#define OUT_SZ   8
#define BPB      32      // batch elements per block
#define NB       8       // batch elements per thread (4 f32x2 pairs)
#define NTHREADS 256     // 64 hidden units * 4 batch-groups

// Shared memory pitches (conflict-free)
#define WP4      97      // float4 pitch per hidden unit j (odd -> conflict-free LDS.128)
#define SHP      36      // h row pitch (floats)
#define SXP      34      // x row pitch (floats)

#define SMEM_FLOATS (HID*WP4*4 + HID*SHP + IN_SZ*SXP)   // 24832 + 2304 + 1088 = 28224
#define SMEM_BYTES  (SMEM_FLOATS * 4)                    // 112896 B

typedef unsigned long long u64t;

__device__ __forceinline__ u64t dup2(float a) {
    u64t r;
    asm("mov.b64 %0, {%1, %1};" : "=l"(r) : "f"(a));
    return r;
}
__device__ __forceinline__ void unpack2(u64t v, float& lo, float& hi) {
    asm("mov.b64 {%0, %1}, %2;" : "=f"(lo), "=f"(hi) : "l"(v));
}
__device__ __forceinline__ void ffma2(u64t& d, u64t a, u64t b) {
    asm("fma.rn.f32x2 %0, %1, %2, %0;" : "+l"(d) : "l"(a), "l"(b));
}

// Accurate, overflow-safe activations (MUFU budget is not the bottleneck)
__device__ __forceinline__ float sigf(float x) {
    return __fdividef(1.0f, 1.0f + __expf(-x));
}
__device__ __forceinline__ float tanh_fast(float x) {
    // 1 - 2/(e^{2x}+1); exact formula, overflow-safe both directions
    return 1.0f - __fdividef(2.0f, __expf(2.0f * x) + 1.0f);
}

__global__ void __launch_bounds__(NTHREADS, 2)
lstm_f32x2_kernel(const float* __restrict__ x,
                  const float* __restrict__ Wih,
                  const float* __restrict__ Whh,
                  const float* __restrict__ bih,
                  const float* __restrict__ bhh,
                  const float* __restrict__ Wfc,
                  const float* __restrict__ bfc,
                  float* __restrict__ out)
{
    extern __shared__ float smem[];
    float4* wpack = (float4*)smem;                 // [HID][WP4] float4: (w_i,w_f,w_g,w_o) per (j, col)
    float*  sh    = smem + HID * WP4 * 4;          // [HID][SHP]: h[k][batch-in-block]
    float*  sx    = sh + HID * SHP;                // [IN_SZ][SXP]: x_t[i][batch-in-block]

    const int tid = threadIdx.x;
    const int j   = tid & 63;        // hidden unit
    const int bg  = tid >> 6;        // batch group (0..3), 8 batches each
    const int batch0 = blockIdx.x * BPB;

    // ---- Prologue: pack weights into smem: wpack[j][i] = {Wih/Whh rows for gates i,f,g,o} ----
    for (int idx = tid; idx < HID * 96; idx += NTHREADS) {
        int jj = idx / 96;
        int i  = idx - jj * 96;
        float4 v;
        if (i < IN_SZ) {
            v.x = Wih[(0 * HID + jj) * IN_SZ + i];
            v.y = Wih[(1 * HID + jj) * IN_SZ + i];
            v.z = Wih[(2 * HID + jj) * IN_SZ + i];
            v.w = Wih[(3 * HID + jj) * IN_SZ + i];
        } else {
            int k = i - IN_SZ;
            v.x = Whh[(0 * HID + jj) * HID + k];
            v.y = Whh[(1 * HID + jj) * HID + k];
            v.z = Whh[(2 * HID + jj) * HID + k];
            v.w = Whh[(3 * HID + jj) * HID + k];
        }
        wpack[jj * WP4 + i] = v;
    }

    // Gate biases (b_ih + b_hh), duplicated for f32x2 lanes
    u64t bias2[4];
#pragma unroll
    for (int g = 0; g < 4; g++)
        bias2[g] = dup2(bih[g * HID + j] + bhh[g * HID + j]);

    // h0 = 0
    for (int idx = tid; idx < HID * SHP; idx += NTHREADS) sh[idx] = 0.0f;

    // Stage x_0: thread -> (batch bb, 4-float chunk)
    const int bb    = tid >> 3;      // 0..31
    const int chunk = tid & 7;       // 0..7  (chunk*4 .. chunk*4+3 of the 32 inputs)
    const float* xbase = x + (size_t)(batch0 + bb) * T_STEPS * IN_SZ;
    {
        float4 v = *(const float4*)(xbase + chunk * 4);
        sx[(chunk * 4 + 0) * SXP + bb] = v.x;
        sx[(chunk * 4 + 1) * SXP + bb] = v.y;
        sx[(chunk * 4 + 2) * SXP + bb] = v.z;
        sx[(chunk * 4 + 3) * SXP + bb] = v.w;
    }

    float c[NB];
#pragma unroll
    for (int b = 0; b < NB; b++) c[b] = 0.0f;

    __syncthreads();

    const float4* wp  = wpack + j * WP4;
    const int     boff = bg * NB;    // this thread's batch offset within the block

    // ---- Recurrence ----
    for (int t = 0; t < T_STEPS; t++) {
        // Prefetch x_{t+1} into registers (hides DRAM latency behind the gate GEMV)
        float4 xn = make_float4(0.f, 0.f, 0.f, 0.f);
        if (t + 1 < T_STEPS)
            xn = *(const float4*)(xbase + (size_t)(t + 1) * IN_SZ + chunk * 4);

        // Gate accumulators: [gate][pair], each f32x2 = 2 batches
        u64t acc[4][4];
#pragma unroll
        for (int g = 0; g < 4; g++)
#pragma unroll
            for (int p = 0; p < 4; p++) acc[g][p] = bias2[g];

        // Input contribution: sum_i x[i] * Wih[g*64+j][i]
#pragma unroll 8
        for (int i = 0; i < IN_SZ; i++) {
            float4 w = wp[i];
            u64t w0 = dup2(w.x), w1 = dup2(w.y), w2 = dup2(w.z), w3 = dup2(w.w);
            const float* xr = sx + i * SXP + boff;
#pragma unroll
            for (int p = 0; p < 4; p++) {
                u64t xv = *(const u64t*)(xr + 2 * p);
                ffma2(acc[0][p], w0, xv);
                ffma2(acc[1][p], w1, xv);
                ffma2(acc[2][p], w2, xv);
                ffma2(acc[3][p], w3, xv);
            }
        }
        // Recurrent contribution: sum_k h[k] * Whh[g*64+j][k]
#pragma unroll 8
        for (int k = 0; k < HID; k++) {
            float4 w = wp[IN_SZ + k];
            u64t w0 = dup2(w.x), w1 = dup2(w.y), w2 = dup2(w.z), w3 = dup2(w.w);
            const float* hr = sh + k * SHP + boff;
#pragma unroll
            for (int p = 0; p < 4; p++) {
                u64t hv = *(const u64t*)(hr + 2 * p);
                ffma2(acc[0][p], w0, hv);
                ffma2(acc[1][p], w1, hv);
                ffma2(acc[2][p], w2, hv);
                ffma2(acc[3][p], w3, hv);
            }
        }

        // Activations + state update (2 batches per pair)
        float hn[NB];
#pragma unroll
        for (int p = 0; p < 4; p++) {
            float gi0, gi1, gf0, gf1, gg0, gg1, go0, go1;
            unpack2(acc[0][p], gi0, gi1);
            unpack2(acc[1][p], gf0, gf1);
            unpack2(acc[2][p], gg0, gg1);
            unpack2(acc[3][p], go0, go1);
            int b0 = 2 * p, b1 = 2 * p + 1;

            float iv0 = sigf(gi0), fv0 = sigf(gf0), gv0 = tanh_fast(gg0), ov0 = sigf(go0);
            c[b0] = fv0 * c[b0] + iv0 * gv0;
            hn[b0] = ov0 * tanh_fast(c[b0]);

            float iv1 = sigf(gi1), fv1 = sigf(gf1), gv1 = tanh_fast(gg1), ov1 = sigf(go1);
            c[b1] = fv1 * c[b1] + iv1 * gv1;
            hn[b1] = ov1 * tanh_fast(c[b1]);
        }

        __syncthreads();   // everyone done reading sh(t) / sx(t)

        // Publish h_{t+1} and x_{t+1}
        *(float4*)(sh + j * SHP + boff)     = make_float4(hn[0], hn[1], hn[2], hn[3]);
        *(float4*)(sh + j * SHP + boff + 4) = make_float4(hn[4], hn[5], hn[6], hn[7]);
        sx[(chunk * 4 + 0) * SXP + bb] = xn.x;
        sx[(chunk * 4 + 1) * SXP + bb] = xn.y;
        sx[(chunk * 4 + 2) * SXP + bb] = xn.z;
        sx[(chunk * 4 + 3) * SXP + bb] = xn.w;

        __syncthreads();
    }

    // ---- Epilogue: out[b] = h_T @ W_fc^T + b_fc ----
    // 256 threads = 32 batches x 8 outputs, exactly one (b, o) per thread.
    {
        const int ob = tid >> 3;   // batch in block
        const int oo = tid & 7;    // output unit
        float s = bfc[oo];
        const float* wrow = Wfc + oo * HID;
#pragma unroll 8
        for (int k = 0; k < HID; k++)
            s += sh[k * SHP + ob] * wrow[k];
        out[(size_t)(batch0 + ob) * OUT_SZ + oo] = s;
    }
}

extern "C" void kernel_launch(void* const* d_in, const int* in_sizes, int n_in,
                              void* d_out, int out_size)
{
    const float* x   = (const float*)d_in[0];
    const float* Wih = (const float*)d_in[1];
    const float* Whh = (const float*)d_in[2];
    const float* bih = (const float*)d_in[3];
    const float* bhh = (const float*)d_in[4];
    const float* Wfc = (const float*)d_in[5];
    const float* bfc = (const float*)d_in[6];
    float* out = (float*)d_out;

    cudaFuncSetAttribute(lstm_f32x2_kernel,
                         cudaFuncAttributeMaxDynamicSharedMemorySize, SMEM_BYTES);

    const int nblocks = 8192 / BPB;   // 256
    lstm_f32x2_kernel<<<nblocks, NTHREADS, SMEM_BYTES>>>(
        x, Wih, Whh, bih, bhh, Wfc, bfc, out);
}

// round 3
// speedup vs baseline: 1.0547x; 1.0547x over previous
#include <cuda_runtime.h>

// Problem constants
#define T_STEPS  128
#define IN_SZ    32
#define HID      64
#define GATES    256     // 4*HID
#define OUT_SZ   8
#define BPB      32      // batch elements per block
#define NB       8       // batch elements per thread (4 f32x2 pairs)
#define NTHREADS 256     // 64 hidden units * 4 batch-groups

// Shared memory pitches (conflict-free)
#define WP4      97      // float4 pitch per hidden unit j (odd -> conflict-free LDS.128)
#define SHP      36      // h row pitch (floats)
#define SXP      34      // x row pitch (floats)

#define SMEM_FLOATS (HID*WP4*4 + HID*SHP + IN_SZ*SXP)
#define SMEM_BYTES  (SMEM_FLOATS * 4)

typedef unsigned long long u64t;

__device__ __forceinline__ u64t dup2(float a) {
    u64t r;
    asm("mov.b64 %0, {%1, %1};" : "=l"(r) : "f"(a));
    return r;
}
__device__ __forceinline__ void unpack2(u64t v, float& lo, float& hi) {
    asm("mov.b64 {%0, %1}, %2;" : "=f"(lo), "=f"(hi) : "l"(v));
}
__device__ __forceinline__ void ffma2(u64t& d, u64t a, u64t b) {
    asm("fma.rn.f32x2 %0, %1, %2, %0;" : "+l"(d) : "l"(a), "l"(b));
}

// Single-MUFU tanh (sm_75+). Abs err ~2^-11 — far inside the 1e-3 budget.
__device__ __forceinline__ float tanh_ap(float x) {
    float y;
    asm("tanh.approx.f32 %0, %1;" : "=f"(y) : "f"(x));
    return y;
}
// sigmoid(2x) = 0.5 + 0.5*tanh(x); caller pre-halves the argument via weight scaling.
__device__ __forceinline__ float sig_from_half(float xh) {
    return fmaf(0.5f, tanh_ap(xh), 0.5f);
}

__global__ void __launch_bounds__(NTHREADS, 2)
lstm_f32x2_kernel(const float* __restrict__ x,
                  const float* __restrict__ Wih,
                  const float* __restrict__ Whh,
                  const float* __restrict__ bih,
                  const float* __restrict__ bhh,
                  const float* __restrict__ Wfc,
                  const float* __restrict__ bfc,
                  float* __restrict__ out)
{
    extern __shared__ float smem[];
    float4* wpack = (float4*)smem;                 // [HID][WP4] float4: (0.5*w_i, 0.5*w_f, w_g, 0.5*w_o)
    float*  sh    = smem + HID * WP4 * 4;          // [HID][SHP]: h[k][batch-in-block]
    float*  sx    = sh + HID * SHP;                // [IN_SZ][SXP]: x_t[i][batch-in-block]

    const int tid = threadIdx.x;
    const int j   = tid & 63;        // hidden unit
    const int bg  = tid >> 6;        // batch group (0..3), 8 batches each
    const int batch0 = blockIdx.x * BPB;

    // ---- Prologue: pack weights (i/f/o pre-scaled by 0.5 for the tanh-sigmoid trick) ----
    for (int idx = tid; idx < HID * 96; idx += NTHREADS) {
        int jj = idx / 96;
        int i  = idx - jj * 96;
        float4 v;
        if (i < IN_SZ) {
            v.x = 0.5f * Wih[(0 * HID + jj) * IN_SZ + i];
            v.y = 0.5f * Wih[(1 * HID + jj) * IN_SZ + i];
            v.z =        Wih[(2 * HID + jj) * IN_SZ + i];
            v.w = 0.5f * Wih[(3 * HID + jj) * IN_SZ + i];
        } else {
            int k = i - IN_SZ;
            v.x = 0.5f * Whh[(0 * HID + jj) * HID + k];
            v.y = 0.5f * Whh[(1 * HID + jj) * HID + k];
            v.z =        Whh[(2 * HID + jj) * HID + k];
            v.w = 0.5f * Whh[(3 * HID + jj) * HID + k];
        }
        wpack[jj * WP4 + i] = v;
    }

    // Gate biases (b_ih + b_hh), i/f/o halved, duplicated for f32x2 lanes
    u64t bias2[4];
    {
        float b0 = 0.5f * (bih[0 * HID + j] + bhh[0 * HID + j]);
        float b1 = 0.5f * (bih[1 * HID + j] + bhh[1 * HID + j]);
        float b2 =        (bih[2 * HID + j] + bhh[2 * HID + j]);
        float b3 = 0.5f * (bih[3 * HID + j] + bhh[3 * HID + j]);
        bias2[0] = dup2(b0); bias2[1] = dup2(b1);
        bias2[2] = dup2(b2); bias2[3] = dup2(b3);
    }

    // h0 = 0
    for (int idx = tid; idx < HID * SHP; idx += NTHREADS) sh[idx] = 0.0f;

    // Stage x_0: thread -> (batch bb, 4-float chunk)
    const int bb    = tid >> 3;      // 0..31
    const int chunk = tid & 7;       // 0..7
    const float* xbase = x + (size_t)(batch0 + bb) * T_STEPS * IN_SZ;
    {
        float4 v = *(const float4*)(xbase + chunk * 4);
        sx[(chunk * 4 + 0) * SXP + bb] = v.x;
        sx[(chunk * 4 + 1) * SXP + bb] = v.y;
        sx[(chunk * 4 + 2) * SXP + bb] = v.z;
        sx[(chunk * 4 + 3) * SXP + bb] = v.w;
    }

    float c[NB];
#pragma unroll
    for (int b = 0; b < NB; b++) c[b] = 0.0f;

    __syncthreads();

    const float4* wp   = wpack + j * WP4;
    const int     boff = bg * NB;

    // ---- Recurrence ----
    for (int t = 0; t < T_STEPS; t++) {
        // Branch-free prefetch of x_{t+1} (clamped; last iteration re-reads x_{T-1}, values unused)
        int tn = t + 1 < T_STEPS ? t + 1 : T_STEPS - 1;
        float4 xn = *(const float4*)(xbase + (size_t)tn * IN_SZ + chunk * 4);

        u64t acc[4][4];
#pragma unroll
        for (int g = 0; g < 4; g++)
#pragma unroll
            for (int p = 0; p < 4; p++) acc[g][p] = bias2[g];

        // Input contribution
#pragma unroll 8
        for (int i = 0; i < IN_SZ; i++) {
            float4 w = wp[i];
            u64t w0 = dup2(w.x), w1 = dup2(w.y), w2 = dup2(w.z), w3 = dup2(w.w);
            const float* xr = sx + i * SXP + boff;
#pragma unroll
            for (int p = 0; p < 4; p++) {
                u64t xv = *(const u64t*)(xr + 2 * p);
                ffma2(acc[0][p], w0, xv);
                ffma2(acc[1][p], w1, xv);
                ffma2(acc[2][p], w2, xv);
                ffma2(acc[3][p], w3, xv);
            }
        }
        // Recurrent contribution
#pragma unroll 8
        for (int k = 0; k < HID; k++) {
            float4 w = wp[IN_SZ + k];
            u64t w0 = dup2(w.x), w1 = dup2(w.y), w2 = dup2(w.z), w3 = dup2(w.w);
            const float* hr = sh + k * SHP + boff;
#pragma unroll
            for (int p = 0; p < 4; p++) {
                u64t hv = *(const u64t*)(hr + 2 * p);
                ffma2(acc[0][p], w0, hv);
                ffma2(acc[1][p], w1, hv);
                ffma2(acc[2][p], w2, hv);
                ffma2(acc[3][p], w3, hv);
            }
        }

        // Activations + state update: 5 MUFU ops per element total
        float hn[NB];
#pragma unroll
        for (int p = 0; p < 4; p++) {
            float gi0, gi1, gf0, gf1, gg0, gg1, go0, go1;
            unpack2(acc[0][p], gi0, gi1);
            unpack2(acc[1][p], gf0, gf1);
            unpack2(acc[2][p], gg0, gg1);
            unpack2(acc[3][p], go0, go1);
            int b0 = 2 * p, b1 = 2 * p + 1;

            float iv0 = sig_from_half(gi0), fv0 = sig_from_half(gf0);
            float gv0 = tanh_ap(gg0),       ov0 = sig_from_half(go0);
            c[b0]  = fmaf(fv0, c[b0], iv0 * gv0);
            hn[b0] = ov0 * tanh_ap(c[b0]);

            float iv1 = sig_from_half(gi1), fv1 = sig_from_half(gf1);
            float gv1 = tanh_ap(gg1),       ov1 = sig_from_half(go1);
            c[b1]  = fmaf(fv1, c[b1], iv1 * gv1);
            hn[b1] = ov1 * tanh_ap(c[b1]);
        }

        __syncthreads();   // everyone done reading sh(t) / sx(t)

        // Publish h_{t+1} and x_{t+1}
        *(float4*)(sh + j * SHP + boff)     = make_float4(hn[0], hn[1], hn[2], hn[3]);
        *(float4*)(sh + j * SHP + boff + 4) = make_float4(hn[4], hn[5], hn[6], hn[7]);
        sx[(chunk * 4 + 0) * SXP + bb] = xn.x;
        sx[(chunk * 4 + 1) * SXP + bb] = xn.y;
        sx[(chunk * 4 + 2) * SXP + bb] = xn.z;
        sx[(chunk * 4 + 3) * SXP + bb] = xn.w;

        __syncthreads();
    }

    // ---- Epilogue: out[b] = h_T @ W_fc^T + b_fc ----
    {
        const int ob = tid >> 3;   // batch in block
        const int oo = tid & 7;    // output unit
        float s = bfc[oo];
        const float* wrow = Wfc + oo * HID;
#pragma unroll 8
        for (int k = 0; k < HID; k++)
            s = fmaf(sh[k * SHP + ob], wrow[k], s);
        out[(size_t)(batch0 + ob) * OUT_SZ + oo] = s;
    }
}

extern "C" void kernel_launch(void* const* d_in, const int* in_sizes, int n_in,
                              void* d_out, int out_size)
{
    const float* x   = (const float*)d_in[0];
    const float* Wih = (const float*)d_in[1];
    const float* Whh = (const float*)d_in[2];
    const float* bih = (const float*)d_in[3];
    const float* bhh = (const float*)d_in[4];
    const float* Wfc = (const float*)d_in[5];
    const float* bfc = (const float*)d_in[6];
    float* out = (float*)d_out;

    cudaFuncSetAttribute(lstm_f32x2_kernel,
                         cudaFuncAttributeMaxDynamicSharedMemorySize, SMEM_BYTES);

    const int nblocks = 8192 / BPB;   // 256
    lstm_f32x2_kernel<<<nblocks, NTHREADS, SMEM_BYTES>>>(
        x, Wih, Whh, bih, bhh, Wfc, bfc, out);
}

// round 12
// speedup vs baseline: 2.0502x; 1.9438x over previous
#include <cuda_runtime.h>
#include <cuda_bf16.h>
#include <cstdint>

// ---------------- Problem constants ----------------
#define T_STEPS  128
#define IN_SZ    32
#define HID      64
#define NGATES   256       // 4*HID (reordered n = 4*j + gate)
#define OUT_SZ   8
#define MTILE    64        // batches per CTA
#define NTHREADS 512       // 16 warps = 4 m-tiles x 4 n-groups
#define NBLOCKS  128       // 8192 / 64

// A/B smem K pitch (elements). K used = 192 (x_hi 0-31 | x_lo 32-63 | h_hi 64-127 | h_lo 128-191).
// Pitch 200 -> row stride 400B -> ldmatrix rows hit all 32 banks (conflict-free).
#define KPAD 200

#define SM_A      0
#define SM_A_SZ   (MTILE * KPAD * 2)        // 25600 B
#define SM_B      SM_A_SZ
#define SM_B_SZ   (NGATES * KPAD * 2)       // 102400 B
#define SM_TOTAL  (SM_A_SZ + SM_B_SZ + 64)  // ~128 KB

// ---------------- helpers ----------------
__device__ __forceinline__ uint32_t smem_u32(const void* p) {
    uint32_t a;
    asm("{ .reg .u64 t; cvta.to.shared.u64 t, %1; cvt.u32.u64 %0, t; }" : "=r"(a) : "l"(p));
    return a;
}
__device__ __forceinline__ float tanh_ap(float x) {
    float y;
    asm("tanh.approx.f32 %0, %1;" : "=f"(y) : "f"(x));
    return y;
}
// split (a,b) fp32 -> packed bf16 hi (truncation via PRMT) + packed bf16 lo (rn residual)
__device__ __forceinline__ void split_pair(float a, float b, uint32_t& hi, uint32_t& lo) {
    uint32_t ba = __float_as_uint(a), bb = __float_as_uint(b);
    asm("prmt.b32 %0, %1, %2, 0x7632;" : "=r"(hi) : "r"(ba), "r"(bb));  // {b.hi16, a.hi16}
    float la = a - __uint_as_float(ba & 0xFFFF0000u);
    float lb = b - __uint_as_float(bb & 0xFFFF0000u);
    asm("cvt.rn.bf16x2.f32 %0, %1, %2;" : "=r"(lo) : "f"(lb), "f"(la)); // lower = la
}
__device__ __forceinline__ void ldsm4(uint32_t& r0, uint32_t& r1, uint32_t& r2, uint32_t& r3,
                                      uint32_t addr) {
    asm volatile("ldmatrix.sync.aligned.m8n8.x4.shared.b16 {%0,%1,%2,%3}, [%4];"
                 : "=r"(r0), "=r"(r1), "=r"(r2), "=r"(r3) : "r"(addr));
}
__device__ __forceinline__ void mma16816(float* d, uint32_t a0, uint32_t a1, uint32_t a2,
                                         uint32_t a3, uint32_t b0, uint32_t b1) {
    asm volatile(
        "mma.sync.aligned.m16n8k16.row.col.f32.bf16.bf16.f32 "
        "{%0,%1,%2,%3}, {%4,%5,%6,%7}, {%8,%9}, {%0,%1,%2,%3};"
        : "+f"(d[0]), "+f"(d[1]), "+f"(d[2]), "+f"(d[3])
        : "r"(a0), "r"(a1), "r"(a2), "r"(a3), "r"(b0), "r"(b1));
}

// Stage x chunk (4 floats at k=ch*4) into A smem as hi (k..) and lo (32+k..)
__device__ __forceinline__ void store_x(__nv_bfloat16* sA, int bb, int ch, float4 v) {
    uint32_t h0, l0, h1, l1;
    split_pair(v.x, v.y, h0, l0);
    split_pair(v.z, v.w, h1, l1);
    uint32_t* p = reinterpret_cast<uint32_t*>(sA + (size_t)bb * KPAD);  // KPAD even -> aligned
    p[2 * ch + 0]      = h0;   // elements k, k+1 (hi)
    p[2 * ch + 1]      = h1;   // k+2, k+3 (hi)
    p[16 + 2 * ch + 0] = l0;   // 32+k..  (lo)
    p[16 + 2 * ch + 1] = l1;
}

__global__ void __launch_bounds__(NTHREADS, 1)
lstm_mma_kernel(const float* __restrict__ x,
                const float* __restrict__ Wih,
                const float* __restrict__ Whh,
                const float* __restrict__ bih,
                const float* __restrict__ bhh,
                const float* __restrict__ Wfc,
                const float* __restrict__ bfc,
                float* __restrict__ out)
{
    extern __shared__ char smem[];
    __nv_bfloat16* sA = reinterpret_cast<__nv_bfloat16*>(smem + SM_A);
    __nv_bfloat16* sB = reinterpret_cast<__nv_bfloat16*>(smem + SM_B);

    const int tid  = threadIdx.x;
    const int lane = tid & 31;
    const int wid  = tid >> 5;
    const int wm   = wid & 3;          // m-tile index (16 rows each)
    const int wn   = wid >> 2;         // n-group index (64 cols each)
    const int m0   = wm * 16;
    const int n0w  = wn * 64;
    const int j0   = wn * 16;

    // ---- Build B tile: [n=4j+g][k], hi/lo split, 0.5-scale for i/f/o gates ----
    for (int idx = tid; idx < NGATES * 192; idx += NTHREADS) {
        int n = idx / 192, k = idx - n * 192;
        int g = n & 3, j = n >> 2;
        float w;
        bool lo;
        if (k < 64) { lo = (k >= 32); w = Wih[(g * HID + j) * IN_SZ + (k & 31)]; }
        else        { lo = (k >= 128); w = Whh[(g * HID + j) * HID + ((k - 64) & 63)]; }
        if (g != 2) w *= 0.5f;
        __nv_bfloat16 hi = __float2bfloat16(w);
        sB[(size_t)n * KPAD + k] = lo ? __float2bfloat16(w - __bfloat162float(hi)) : hi;
    }
    // Zero A (h=0, padding)
    {
        uint32_t* pA = reinterpret_cast<uint32_t*>(sA);
        for (int idx = tid; idx < MTILE * KPAD / 2; idx += NTHREADS) pA[idx] = 0u;
    }
    __syncthreads();

    // ---- Stage x(0) ----
    const int bb = tid >> 3;           // batch-in-block (0..63)
    const int ch = tid & 7;            // 4-float chunk (0..7)
    const float4* xrow = reinterpret_cast<const float4*>(
        x + (size_t)(blockIdx.x * MTILE + bb) * T_STEPS * IN_SZ);
    store_x(sA, bb, ch, xrow[ch]);     // t=0

    // ---- Per-thread fp32 gate biases (16 cols: 8 n-tiles x 2 cols) ----
    float barr[16];
#pragma unroll
    for (int nt = 0; nt < 8; nt++)
#pragma unroll
        for (int cc = 0; cc < 2; cc++) {
            int ncol = n0w + nt * 8 + (lane & 3) * 2 + cc;
            int g = ncol & 3, j = ncol >> 2;
            float bv = bih[g * HID + j] + bhh[g * HID + j];
            barr[nt * 2 + cc] = (g == 2) ? bv : 0.5f * bv;
        }

    float c[8];
#pragma unroll
    for (int i = 0; i < 8; i++) c[i] = 0.0f;

    // ---- ldmatrix lane base addresses ----
    const int tt = lane >> 3, rr = lane & 7;
    const uint32_t sA_u = smem_u32(sA), sB_u = smem_u32(sB);
    // A (row-major [m][k]): matrices (m0-7,k0),(m8-15,k0),(m0-7,k8),(m8-15,k8)
    const uint32_t a_base = sA_u +
        (((uint32_t)(m0 + (tt & 1) * 8 + rr) * KPAD + (uint32_t)((tt >> 1) * 8)) * 2u);
    // B (k-contiguous [n][k] == the col-major K x N the mma wants; NO trans):
    // matrices (n0-7,k0),(n0-7,k8),(n8-15,k0),(n8-15,k8) -> regs b0,b1,b2,b3
    const uint32_t b_base = sB_u +
        (((uint32_t)(n0w + (tt >> 1) * 8 + rr) * KPAD + (uint32_t)((tt & 1) * 8)) * 2u);

    const bool evenq = (lane & 1) == 0;

    __syncthreads();

    // ---- Recurrence ----
    for (int t = 0; t < T_STEPS; t++) {
        // Prefetch x(t+1)
        int tn = (t + 1 < T_STEPS) ? t + 1 : T_STEPS - 1;
        float4 xn = xrow[(size_t)tn * 8 + ch];

        // Accumulators init = exact fp32 bias
        float d[32];
#pragma unroll
        for (int nt = 0; nt < 8; nt++) {
            d[4 * nt + 0] = barr[2 * nt + 0];
            d[4 * nt + 1] = barr[2 * nt + 1];
            d[4 * nt + 2] = barr[2 * nt + 0];
            d[4 * nt + 3] = barr[2 * nt + 1];
        }

        // K-chunk schedule: x_hi*W_hi, x_hi*W_lo, x_lo*W_hi, h_hi*W_hi, h_hi*W_lo, h_lo*W_hi
        const int AK[18] = {0,16,  0,16, 32,48,  64,80,96,112,  64,80,96,112, 128,144,160,176};
        const int BK[18] = {0,16, 32,48,  0,16,  64,80,96,112, 128,144,160,176, 64,80,96,112};

#pragma unroll
        for (int kc = 0; kc < 18; kc++) {
            uint32_t a0, a1, a2, a3;
            ldsm4(a0, a1, a2, a3, a_base + (uint32_t)AK[kc] * 2u);
#pragma unroll
            for (int ns = 0; ns < 4; ns++) {
                uint32_t b0, b1, b2, b3;
                ldsm4(b0, b1, b2, b3,
                      b_base + (uint32_t)BK[kc] * 2u + (uint32_t)(ns * 16 * KPAD * 2));
                mma16816(d + (2 * ns) * 4,     a0, a1, a2, a3, b0, b1);
                mma16816(d + (2 * ns + 1) * 4, a0, a1, a2, a3, b2, b3);
            }
        }

        // ---- Pointwise epilogue ----
        // cols: q=lane&3; q even -> gates (i,f), q odd -> (g,o) of same j.
        // Pair exchange (lane^1): even thread keeps row r, odd keeps row r+8.
        float hv[8];
#pragma unroll
        for (int nt = 0; nt < 8; nt++) {
            float d0 = d[4 * nt + 0], d1 = d[4 * nt + 1];
            float d2 = d[4 * nt + 2], d3 = d[4 * nt + 3];
            float s1 = evenq ? d2 : d0;
            float s2 = evenq ? d3 : d1;
            float rx1 = __shfl_xor_sync(0xFFFFFFFFu, s1, 1);
            float rx2 = __shfl_xor_sync(0xFFFFFFFFu, s2, 1);
            float gi = evenq ? d0  : rx1;
            float gf = evenq ? d1  : rx2;
            float gg = evenq ? rx1 : d2;
            float go = evenq ? rx2 : d3;
            float iv = fmaf(0.5f, tanh_ap(gi), 0.5f);
            float fv = fmaf(0.5f, tanh_ap(gf), 0.5f);
            float gv = tanh_ap(gg);
            float ov = fmaf(0.5f, tanh_ap(go), 0.5f);
            c[nt] = fmaf(fv, c[nt], iv * gv);
            hv[nt] = ov * tanh_ap(c[nt]);
        }

        __syncthreads();   // all warps done reading A(t)

        // Publish h(t+1): hi (trunc) at k=64+j, lo (rn residual) at k=128+j
        {
            int hrow = m0 + (lane >> 2) + (evenq ? 0 : 8);
            uint16_t* sA16 = reinterpret_cast<uint16_t*>(sA);
#pragma unroll
            for (int nt = 0; nt < 8; nt++) {
                int j = j0 + 2 * nt + ((lane & 3) >> 1);
                uint32_t hb = __float_as_uint(hv[nt]);
                sA16[(size_t)hrow * KPAD + 64 + j] = (uint16_t)(hb >> 16);
                sA[(size_t)hrow * KPAD + 128 + j] =
                    __float2bfloat16(hv[nt] - __uint_as_float(hb & 0xFFFF0000u));
            }
        }
        // Publish x(t+1)
        store_x(sA, bb, ch, xn);

        __syncthreads();
    }

    // ---- FC epilogue: out[b,o] = h_T[b,:] @ Wfc[o,:] + bfc[o]; one (b,o) per thread ----
    {
        const int b = tid >> 3, o = tid & 7;
        const uint16_t* sA16 = reinterpret_cast<const uint16_t*>(sA);
        float s = bfc[o];
        const float* wr = Wfc + o * HID;
#pragma unroll 8
        for (int j = 0; j < HID; j++) {
            float hj = __uint_as_float(((uint32_t)sA16[(size_t)b * KPAD + 64 + j]) << 16)
                     + __bfloat162float(sA[(size_t)b * KPAD + 128 + j]);
            s = fmaf(hj, wr[j], s);
        }
        out[(size_t)(blockIdx.x * MTILE + b) * OUT_SZ + o] = s;
    }
}

extern "C" void kernel_launch(void* const* d_in, const int* in_sizes, int n_in,
                              void* d_out, int out_size)
{
    const float* x   = (const float*)d_in[0];
    const float* Wih = (const float*)d_in[1];
    const float* Whh = (const float*)d_in[2];
    const float* bih = (const float*)d_in[3];
    const float* bhh = (const float*)d_in[4];
    const float* Wfc = (const float*)d_in[5];
    const float* bfc = (const float*)d_in[6];
    float* out = (float*)d_out;

    cudaFuncSetAttribute(lstm_mma_kernel,
                         cudaFuncAttributeMaxDynamicSharedMemorySize, SM_TOTAL);

    lstm_mma_kernel<<<NBLOCKS, NTHREADS, SM_TOTAL>>>(
        x, Wih, Whh, bih, bhh, Wfc, bfc, out);
}